// round 16
// baseline (speedup 1.0000x reference)
#include <cuda_runtime.h>

#define NN 20000      // nodes
#define NE 100000     // edges
#define NF 64         // node feature dim (in) — 64 for every layer here
#define EFD 32        // edge feature dim
#define FH 128        // heads * out_dim = 2*64
#define NH 2          // heads
#define DH 64         // out dim per head

// per-layer weights in constant memory (copied per layer, D2D; validated R12)
#define WN_OFF 0
#define WE_OFF 8192
#define B_OFF  12288
__constant__ float cW[12416];   // Wn[64*128] | We[32*128] | b[128]

// ---------------- scratch (device globals) ----------------------------------
__device__ __align__(16) float g_elb[2][NN * NH]; // double-buffered el
__device__ __align__(16) float g_erb[2][NN * NH]; // double-buffered er
__device__ __align__(16) float g_h [NN * NF];
__device__ __align__(16) float g_h2[NN * NF];
__device__ __align__(16) float g_Wp[NF * FH];     // W_e2d^T @ Wn_dec0
__device__ __align__(16) float g_efs[NE * EFD];   // ef rows in CSR order
__device__ __align__(8)  float g_eeall[4][NE * NH]; // ee per layer, CSR order
__device__ int g_srcs[NE];                        // src in CSR order
// reduced attention weights per layer
__device__ float g_redl[4][NH * NF];
__device__ float g_redr[4][NH * NF];
__device__ float g_rede[4][NH * EFD];
// CSR (dst -> edges), natural node order (sorting proven unhelpful R14/R15)
__device__ int g_deg[NN];        // zero-init at load; scan re-zeroes each call
__device__ int g_off[NN + 1];
__device__ int g_cur[NN];

struct PrepParams {
    const float *Wn[4], *We[4], *al[4], *ar[4], *ae[4];
    const float* We2d;
};

// ================= pre1: hist + wfuse + prep (fused) ========================
#define B_HIST 391     // ceil(NE/256)
#define B_WF   32      // NF*FH/256
#define B_PREP 12      // 4 layers * 3 matrices
__global__ __launch_bounds__(256) void pre1_kernel(
        const int* __restrict__ dst, PrepParams pp)
{
    const int t = threadIdx.x;
    const int b = blockIdx.x;
    if (b < B_HIST) {                              // ---- histogram
        const int e = b * 256 + t;
        if (e < NE) atomicAdd(&g_deg[dst[e]], 1);
    } else if (b < B_HIST + B_WF) {                // ---- Wp = W_e2d^T @ Wn_dec0
        const int i = (b - B_HIST) * 256 + t;      // m*128 + c
        const int m = i >> 7, c = i & 127;
        float v = 0.f;
#pragma unroll
        for (int k = 0; k < NF; k++)
            v = fmaf(pp.We2d[k * NF + m], pp.Wn[2][k * FH + c], v);
        g_Wp[m * FH + c] = v;
    } else {                                       // ---- reduced attn weights
        const int bid2 = b - B_HIST - B_WF;
        const int lid = bid2 / 3, mat = bid2 % 3;
        __shared__ float stt[128];
        if (mat < 2) {                             // redl / redr
            const float* a = mat ? pp.ar[lid] : pp.al[lid];
            float v = 0.f;
            if (t < 128) {
                const int h = t >> 6, k = t & 63;
#pragma unroll
                for (int d = 0; d < DH; d++)
                    v = fmaf(pp.Wn[lid][k * FH + h * DH + d], a[h * DH + d], v);
                if (lid == 2) stt[t] = v;          // two-step for dec0 (e2d fused)
                else (mat ? g_redr : g_redl)[lid][(t >> 6) * NF + (t & 63)] = v;
            }
            if (lid == 2) {
                __syncthreads();
                if (t < 128) {
                    const int h = t >> 6, m = t & 63;
                    float w = 0.f;
#pragma unroll
                    for (int k = 0; k < NF; k++)
                        w = fmaf(pp.We2d[k * NF + m], stt[h * 64 + k], w);
                    (mat ? g_redr : g_redl)[2][h * NF + m] = w;
                }
            }
        } else if (t < NH * EFD) {                 // rede
            const int h = t >> 5, k = t & 31;
            float v = 0.f;
#pragma unroll
            for (int d = 0; d < DH; d++)
                v = fmaf(pp.We[lid][k * FH + h * DH + d], pp.ae[lid][h * DH + d], v);
            g_rede[lid][h * EFD + k] = v;
        }
    }
}

// ================= scan: smem-staged coalesced prefix sum (no sort) =========
#define SCAN_T 1024
#define CHUNK 20
__global__ __launch_bounds__(SCAN_T) void scan_kernel()
{
    extern __shared__ int si[];
    int* sdeg = si;                 // NN
    int* sp   = si + NN;            // 1024
    int* sb   = si + NN + 1024;     // 1024
    const int t = threadIdx.x;
    for (int i = t; i < NN; i += SCAN_T) { sdeg[i] = g_deg[i]; g_deg[i] = 0; }
    __syncthreads();
    const int base = t * CHUNK;
    int sum = 0;
#pragma unroll
    for (int i = 0; i < CHUNK; i++) {
        const int idx = base + i;
        if (idx < NN) {
            const int d = sdeg[idx];
            sdeg[idx] = sum;        // exclusive prefix within chunk
            sum += d;
        }
    }
    sp[t] = sum;
    __syncthreads();
    for (int o = 1; o < SCAN_T; o <<= 1) {
        int v = 0;
        if (t >= o) v = sp[t - o];
        __syncthreads();
        if (t >= o) sp[t] += v;
        __syncthreads();
    }
    sb[t] = sp[t] - sum;            // exclusive base per chunk
    __syncthreads();
    for (int i = t; i < NN; i += SCAN_T) {
        const int v = sdeg[i] + sb[i / CHUNK];
        g_off[i] = v;
        g_cur[i] = v;
    }
    if (t == SCAN_T - 1) g_off[NN] = sp[SCAN_T - 1];
}
#define SCAN_SMEM ((NN + 2 * SCAN_T) * 4)

// ================= pre2: scatterF + layer-0 el/er (fused) ===================
#define B_SCAT 391     // ceil(NE/256)
#define B_NA   313     // ceil(NN/64)
__global__ __launch_bounds__(256) void pre2_kernel(
        const int* __restrict__ dst, const int* __restrict__ src,
        const float* __restrict__ ef, const float* __restrict__ x)
{
    __shared__ float smf[64 * 65];
    const int t = threadIdx.x;
    const int b = blockIdx.x;
    if (b < B_SCAT) {
        // ---- scatter + gather + 4-layer ee
        float* srd = smf;                       // [4][NH*EFD] = 256
        if (t < 4 * NH * EFD) srd[t] = ((const float*)g_rede)[t];
        __syncthreads();
        const int e = b * 256 + t;
        if (e >= NE) return;
        const int pos = atomicAdd(&g_cur[dst[e]], 1);
        g_srcs[pos] = src[e];
        float r[EFD];
#pragma unroll
        for (int q = 0; q < EFD / 4; q++) {
            const float4 v = __ldg((const float4*)&ef[(size_t)e * EFD + q * 4]);
            r[q * 4 + 0] = v.x; r[q * 4 + 1] = v.y;
            r[q * 4 + 2] = v.z; r[q * 4 + 3] = v.w;
            *(float4*)&g_efs[(size_t)pos * EFD + q * 4] = v;
        }
#pragma unroll
        for (int lid = 0; lid < 4; lid++) {
            float v0 = 0.f, v1 = 0.f;
#pragma unroll
            for (int k = 0; k < EFD; k++) {
                v0 = fmaf(r[k], srd[lid * 64 + k], v0);
                v1 = fmaf(r[k], srd[lid * 64 + EFD + k], v1);
            }
            *(float2*)&g_eeall[lid][(size_t)pos * NH] = make_float2(v0, v1);
        }
    } else {
        // ---- layer-0 el/er for 64 nodes
        const int n0 = (b - B_SCAT) * 64;
        for (int i = t; i < 64 * NF; i += 256) {
            const int row = i >> 6, col = i & 63;
            const int n = n0 + row;
            smf[row * 65 + col] = (n < NN) ? x[(size_t)n * NF + col] : 0.f;
        }
        __syncthreads();
        const int type = t >> 7, h = (t >> 6) & 1, i = t & 63;
        const int n = n0 + i;
        if (n < NN) {
            const float* rd = (type ? g_redr : g_redl)[0] + h * NF;
            float v = 0.f;
#pragma unroll
            for (int k = 0; k < NF; k++) v = fmaf(smf[i * 65 + k], rd[k], v);
            (type ? g_erb : g_elb)[0][n * NH + h] = v;
        }
    }
}

// ================= fused per-layer kernel ====================================
// 512 threads, 32 nodes/block, grid 625.
// Phase A: half-warp per node (R13 known-good form); 1/s folded; transposed
//          store to sV (stride 33 -> conflict-free both directions).
// Phase B: lane = row, warp = 8 UNIFORM columns. Per k per warp:
//          2 uniform LDC.128 (constant port, zero L1) + 1 conflict-free LDS
//          for 256 FMAs -> Phase B L1 wavefronts ~3x fewer, weight LDGs gone.
// Phase C: head-mean -> hout; next-layer el/er epilogue.
#define SVS 33                     // sV row stride
#define STS_ 129                   // st row stride
__global__ __launch_bounds__(512) void layer_kernel(
        const float* __restrict__ x,
        const float* __restrict__ el_in, const float* __restrict__ er_in,
        float* __restrict__ el_out, float* __restrict__ er_out,
        int lid, int last, float* __restrict__ hout)
{
    __shared__ float sV[192 * SVS];   // [k][i]; k<128 xs(h*64+kk), k>=128 us
    __shared__ float st[32 * STS_];   // [i][c]

    const int t = threadIdx.x;
    const int wid = t >> 5, lane = t & 31;
    const int half = lane >> 4, s = lane & 15;
    const int i = wid * 2 + half;                 // block-local node 0..31
    const int n0 = blockIdx.x * 32;
    const int n = n0 + i;
    const float* eep = g_eeall[lid];

    const float2 er2 = *(const float2*)&er_in[n * NH];
    const int start = g_off[n];
    const int deg = g_off[n + 1] - start;
    const int dother = __shfl_xor_sync(0xffffffffu, deg, 16);
    const int degmax = (deg > dother) ? deg : dother;

    float4 xa0 = make_float4(0.f, 0.f, 0.f, 0.f);   // head-0 weighted x sums
    float4 xa1 = make_float4(0.f, 0.f, 0.f, 0.f);   // head-1
    float2 ua0 = make_float2(0.f, 0.f);
    float2 ua1 = make_float2(0.f, 0.f);
    float s0 = 0.f, s1 = 0.f;

    for (int jj = 0; jj < degmax; jj += 2) {
        // two edge slots, index-clamped so loads stay in-bounds
        int o0 = jj;     if (o0 > deg - 1) o0 = deg - 1; if (o0 < 0) o0 = 0;
        int o1 = jj + 1; if (o1 > deg - 1) o1 = deg - 1; if (o1 < 0) o1 = 0;
        int j0 = start + o0; if (j0 > NE - 1) j0 = NE - 1;
        int j1 = start + o1; if (j1 > NE - 1) j1 = NE - 1;
        const bool a0 = (jj < deg), a1 = (jj + 1 < deg);

        const int sn0 = g_srcs[j0], sn1 = g_srcs[j1];
        const float2 ee0 = *(const float2*)&eep[(size_t)j0 * NH];
        const float2 ee1 = *(const float2*)&eep[(size_t)j1 * NH];
        const float2 eA = *(const float2*)&el_in[sn0 * NH];
        const float2 eB = *(const float2*)&el_in[sn1 * NH];
        const float4 xv0 = __ldg((const float4*)&x[(size_t)sn0 * NF + s * 4]);
        const float4 xv1 = __ldg((const float4*)&x[(size_t)sn1 * NF + s * 4]);
        const float2 ev0 = *(const float2*)&g_efs[(size_t)j0 * EFD + s * 2];
        const float2 ev1 = *(const float2*)&g_efs[(size_t)j1 * EFD + s * 2];

        float l00 = eA.x + er2.x + ee0.x, l01 = eA.y + er2.y + ee0.y;
        float l10 = eB.x + er2.x + ee1.x, l11 = eB.y + er2.y + ee1.y;
        l00 = (l00 > 0.f) ? l00 : 0.2f * l00;
        l01 = (l01 > 0.f) ? l01 : 0.2f * l01;
        l10 = (l10 > 0.f) ? l10 : 0.2f * l10;
        l11 = (l11 > 0.f) ? l11 : 0.2f * l11;
        const float p00 = a0 ? __expf(l00) : 0.f;
        const float p01 = a0 ? __expf(l01) : 0.f;
        const float p10 = a1 ? __expf(l10) : 0.f;
        const float p11 = a1 ? __expf(l11) : 0.f;
        s0 += p00 + p10; s1 += p01 + p11;

        xa0.x = fmaf(xv0.x, p00, fmaf(xv1.x, p10, xa0.x));
        xa0.y = fmaf(xv0.y, p00, fmaf(xv1.y, p10, xa0.y));
        xa0.z = fmaf(xv0.z, p00, fmaf(xv1.z, p10, xa0.z));
        xa0.w = fmaf(xv0.w, p00, fmaf(xv1.w, p10, xa0.w));
        xa1.x = fmaf(xv0.x, p01, fmaf(xv1.x, p11, xa1.x));
        xa1.y = fmaf(xv0.y, p01, fmaf(xv1.y, p11, xa1.y));
        xa1.z = fmaf(xv0.z, p01, fmaf(xv1.z, p11, xa1.z));
        xa1.w = fmaf(xv0.w, p01, fmaf(xv1.w, p11, xa1.w));
        ua0.x = fmaf(ev0.x, p00, fmaf(ev1.x, p10, ua0.x));
        ua0.y = fmaf(ev0.y, p00, fmaf(ev1.y, p10, ua0.y));
        ua1.x = fmaf(ev0.x, p01, fmaf(ev1.x, p11, ua1.x));
        ua1.y = fmaf(ev0.y, p01, fmaf(ev1.y, p11, ua1.y));
    }

    const float inv0 = (s0 > 0.f) ? 1.f / s0 : 0.f;   // deg-0 -> msg = 0
    const float inv1 = (s1 > 0.f) ? 1.f / s1 : 0.f;
    sV[(4 * s + 0) * SVS + i] = xa0.x * inv0;
    sV[(4 * s + 1) * SVS + i] = xa0.y * inv0;
    sV[(4 * s + 2) * SVS + i] = xa0.z * inv0;
    sV[(4 * s + 3) * SVS + i] = xa0.w * inv0;
    sV[(64 + 4 * s + 0) * SVS + i] = xa1.x * inv1;
    sV[(64 + 4 * s + 1) * SVS + i] = xa1.y * inv1;
    sV[(64 + 4 * s + 2) * SVS + i] = xa1.z * inv1;
    sV[(64 + 4 * s + 3) * SVS + i] = xa1.w * inv1;
    sV[(128 + 2 * s + 0) * SVS + i] = ua0.x * inv0;
    sV[(128 + 2 * s + 1) * SVS + i] = ua0.y * inv0;
    sV[(160 + 2 * s + 0) * SVS + i] = ua1.x * inv1;
    sV[(160 + 2 * s + 1) * SVS + i] = ua1.y * inv1;
    __syncthreads();

    // -------- Phase B: lane = row (32 rows); warp = 8 uniform columns --------
    {
        const int c0 = wid * 8;                   // uniform within warp
        const int h = wid >> 3;                   // wid 0..7 -> h0, 8..15 -> h1
        float acc[8];
#pragma unroll
        for (int r = 0; r < 8; r++) acc[r] = 0.f;

        const float* sVx = sV + (h * 64) * SVS + lane;
#pragma unroll 4
        for (int kk = 0; kk < NF; kk++) {
            const float a = sVx[kk * SVS];
            const float4 w0 = *(const float4*)&cW[WN_OFF + kk * FH + c0];
            const float4 w1 = *(const float4*)&cW[WN_OFF + kk * FH + c0 + 4];
            acc[0] = fmaf(a, w0.x, acc[0]); acc[1] = fmaf(a, w0.y, acc[1]);
            acc[2] = fmaf(a, w0.z, acc[2]); acc[3] = fmaf(a, w0.w, acc[3]);
            acc[4] = fmaf(a, w1.x, acc[4]); acc[5] = fmaf(a, w1.y, acc[5]);
            acc[6] = fmaf(a, w1.z, acc[6]); acc[7] = fmaf(a, w1.w, acc[7]);
        }
        const float* sVu = sV + (128 + h * 32) * SVS + lane;
#pragma unroll 4
        for (int kk = 0; kk < EFD; kk++) {
            const float a = sVu[kk * SVS];
            const float4 w0 = *(const float4*)&cW[WE_OFF + kk * FH + c0];
            const float4 w1 = *(const float4*)&cW[WE_OFF + kk * FH + c0 + 4];
            acc[0] = fmaf(a, w0.x, acc[0]); acc[1] = fmaf(a, w0.y, acc[1]);
            acc[2] = fmaf(a, w0.z, acc[2]); acc[3] = fmaf(a, w0.w, acc[3]);
            acc[4] = fmaf(a, w1.x, acc[4]); acc[5] = fmaf(a, w1.y, acc[5]);
            acc[6] = fmaf(a, w1.z, acc[6]); acc[7] = fmaf(a, w1.w, acc[7]);
        }
#pragma unroll
        for (int r = 0; r < 8; r++)
            st[lane * STS_ + c0 + r] = acc[r] + cW[B_OFF + c0 + r];
    }
    __syncthreads();

    // -------- Phase C: head mean -> hout (32*64 outputs, 4 per thread) ------
#pragma unroll
    for (int rep = 0; rep < 4; rep++) {
        const int idx = rep * 512 + t;
        const int ii = idx >> 6, d = idx & 63;
        hout[(size_t)(n0 + ii) * DH + d] =
            0.5f * (st[ii * STS_ + d] + st[ii * STS_ + DH + d]);
    }
    // next-layer el/er (128 tasks: type x head x 32 nodes)
    if (!last && t < 128) {
        const int type = t >> 6, hh = (t >> 5) & 1, ii = t & 31;
        const float* rd = (type ? g_redr : g_redl)[lid + 1] + hh * NF;
        float v = 0.f;
#pragma unroll
        for (int d = 0; d < DH; d++)
            v = fmaf(0.5f * (st[ii * STS_ + d] + st[ii * STS_ + DH + d]), rd[d], v);
        (type ? er_out : el_out)[(n0 + ii) * NH + hh] = v;
    }
}

// ---------------- host-side driver ------------------------------------------
static void load_weights(const float* Wn, const float* We, const float* b)
{
    cudaMemcpyToSymbolAsync(cW, Wn, NF * FH * sizeof(float), WN_OFF * sizeof(float),
                            cudaMemcpyDeviceToDevice, 0);
    cudaMemcpyToSymbolAsync(cW, We, EFD * FH * sizeof(float), WE_OFF * sizeof(float),
                            cudaMemcpyDeviceToDevice, 0);
    cudaMemcpyToSymbolAsync(cW, b, FH * sizeof(float), B_OFF * sizeof(float),
                            cudaMemcpyDeviceToDevice, 0);
}

extern "C" void kernel_launch(void* const* d_in, const int* in_sizes, int n_in,
                              void* d_out, int out_size)
{
    const float* x   = (const float*)d_in[0];
    const float* e   = (const float*)d_in[1];
    const int*   src = (const int*)  d_in[2];
    const int*   dst = (const int*)  d_in[3];

    // Only the LAST snapshot contributes to the output (decoded[-1]).
    const int S = in_sizes[0] / (NN * NF);
    const float* xs = x   + (size_t)(S - 1) * NN * NF;
    const float* es = e   + (size_t)(S - 1) * NE * EFD;
    const int*   ss = src + (size_t)(S - 1) * NE;
    const int*   ds = dst + (size_t)(S - 1) * NE;

    void *ph = nullptr, *ph2 = nullptr, *pwp = nullptr, *pel = nullptr, *per = nullptr;
    cudaGetSymbolAddress(&ph,  g_h);
    cudaGetSymbolAddress(&ph2, g_h2);
    cudaGetSymbolAddress(&pwp, g_Wp);
    cudaGetSymbolAddress(&pel, g_elb);
    cudaGetSymbolAddress(&per, g_erb);
    float* h  = (float*)ph;
    float* h2 = (float*)ph2;
    const float* Wp = (const float*)pwp;
    float* elb[2] = { (float*)pel, (float*)pel + NN * NH };
    float* erb[2] = { (float*)per, (float*)per + NN * NH };

    cudaFuncSetAttribute(scan_kernel, cudaFuncAttributeMaxDynamicSharedMemorySize,
                         SCAN_SMEM);

    // Input order (setup_inputs dict insertion order):
    //   0:x 1:e 2:src 3:dst, 4..9:enc0{Wn,We,al,ar,ae,b}, 10..15:enc1,
    //   16..21:dec0, 22..27:dec1, 28:W_e2d
    const float* P[29];
    for (int i = 4; i <= 28; i++) P[i] = (const float*)d_in[i];

    PrepParams pp;
    pp.Wn[0] = P[4];  pp.We[0] = P[5];  pp.al[0] = P[6];  pp.ar[0] = P[7];  pp.ae[0] = P[8];
    pp.Wn[1] = P[10]; pp.We[1] = P[11]; pp.al[1] = P[12]; pp.ar[1] = P[13]; pp.ae[1] = P[14];
    pp.Wn[2] = P[16]; pp.We[2] = P[17]; pp.al[2] = P[18]; pp.ar[2] = P[19]; pp.ae[2] = P[20];
    pp.Wn[3] = P[22]; pp.We[3] = P[23]; pp.al[3] = P[24]; pp.ar[3] = P[25]; pp.ae[3] = P[26];
    pp.We2d = P[28];

    pre1_kernel<<<B_HIST + B_WF + B_PREP, 256>>>(ds, pp);
    scan_kernel<<<1, SCAN_T, SCAN_SMEM>>>();
    pre2_kernel<<<B_SCAT + B_NA, 256>>>(ds, ss, es, xs);

    // layer 0 (enc0)
    load_weights(P[4], P[5], P[9]);
    layer_kernel<<<NN / 32, 512>>>(xs, elb[0], erb[0], elb[1], erb[1], 0, 0, h);
    // layer 1 (enc1)
    load_weights(P[10], P[11], P[15]);
    layer_kernel<<<NN / 32, 512>>>(h, elb[1], erb[1], elb[0], erb[0], 1, 0, h2);
    // layer 2 (dec0, e2d fused via Wp)
    load_weights(Wp, P[17], P[21]);
    layer_kernel<<<NN / 32, 512>>>(h2, elb[0], erb[0], elb[1], erb[1], 2, 0, h);
    // layer 3 (dec1)
    load_weights(P[22], P[23], P[27]);
    layer_kernel<<<NN / 32, 512>>>(h, elb[1], erb[1], elb[0], erb[0], 3, 1, (float*)d_out);
}

// round 17
// speedup vs baseline: 2.2478x; 2.2478x over previous
#include <cuda_runtime.h>

#define NN 20000      // nodes
#define NE 100000     // edges
#define NF 64         // node feature dim (in) — 64 for every layer here
#define EFD 32        // edge feature dim
#define FH 128        // heads * out_dim = 2*64
#define NH 2          // heads
#define DH 64         // out dim per head

// ---------------- scratch (device globals) ----------------------------------
__device__ __align__(16) float g_elb[2][NN * NH]; // double-buffered el
__device__ __align__(16) float g_erb[2][NN * NH]; // double-buffered er
__device__ __align__(16) float g_h [NN * NF];
__device__ __align__(16) float g_h2[NN * NF];
__device__ __align__(16) float g_Wp[NF * FH];     // W_e2d^T @ Wn_dec0
__device__ __align__(16) float g_efs[NE * EFD];   // ef rows in CSR order
__device__ __align__(8)  float g_eeall[4][NE * NH]; // ee per layer, CSR order
__device__ int g_srcs[NE];                        // src in CSR order
// reduced attention weights per layer
__device__ float g_redl[4][NH * NF];
__device__ float g_redr[4][NH * NF];
__device__ float g_rede[4][NH * EFD];
// CSR (dst -> edges), natural node order
__device__ int g_deg[NN];        // zero-init at load; scan re-zeroes each call
__device__ int g_off[NN + 1];
__device__ int g_cur[NN];

struct PrepParams {
    const float *Wn[4], *We[4], *al[4], *ar[4], *ae[4];
    const float* We2d;
};

// ================= pre1: hist + wfuse + prep (fused) ========================
#define B_HIST 391     // ceil(NE/256)
#define B_WF   32      // NF*FH/256
#define B_PREP 12      // 4 layers * 3 matrices
__global__ __launch_bounds__(256) void pre1_kernel(
        const int* __restrict__ dst, PrepParams pp)
{
    const int t = threadIdx.x;
    const int b = blockIdx.x;
    if (b < B_HIST) {                              // ---- histogram
        const int e = b * 256 + t;
        if (e < NE) atomicAdd(&g_deg[dst[e]], 1);
    } else if (b < B_HIST + B_WF) {                // ---- Wp = W_e2d^T @ Wn_dec0
        const int i = (b - B_HIST) * 256 + t;      // m*128 + c
        const int m = i >> 7, c = i & 127;
        float v = 0.f;
#pragma unroll
        for (int k = 0; k < NF; k++)
            v = fmaf(pp.We2d[k * NF + m], pp.Wn[2][k * FH + c], v);
        g_Wp[m * FH + c] = v;
    } else {                                       // ---- reduced attn weights
        const int bid2 = b - B_HIST - B_WF;
        const int lid = bid2 / 3, mat = bid2 % 3;
        __shared__ float stt[128];
        if (mat < 2) {                             // redl / redr
            const float* a = mat ? pp.ar[lid] : pp.al[lid];
            float v = 0.f;
            if (t < 128) {
                const int h = t >> 6, k = t & 63;
#pragma unroll
                for (int d = 0; d < DH; d++)
                    v = fmaf(pp.Wn[lid][k * FH + h * DH + d], a[h * DH + d], v);
                if (lid == 2) stt[t] = v;          // two-step for dec0 (e2d fused)
                else (mat ? g_redr : g_redl)[lid][(t >> 6) * NF + (t & 63)] = v;
            }
            if (lid == 2) {
                __syncthreads();
                if (t < 128) {
                    const int h = t >> 6, m = t & 63;
                    float w = 0.f;
#pragma unroll
                    for (int k = 0; k < NF; k++)
                        w = fmaf(pp.We2d[k * NF + m], stt[h * 64 + k], w);
                    (mat ? g_redr : g_redl)[2][h * NF + m] = w;
                }
            }
        } else if (t < NH * EFD) {                 // rede
            const int h = t >> 5, k = t & 31;
            float v = 0.f;
#pragma unroll
            for (int d = 0; d < DH; d++)
                v = fmaf(pp.We[lid][k * FH + h * DH + d], pp.ae[lid][h * DH + d], v);
            g_rede[lid][h * EFD + k] = v;
        }
    }
}

// ================= scan: smem-staged coalesced prefix sum ====================
#define SCAN_T 1024
#define CHUNK 20
__global__ __launch_bounds__(SCAN_T) void scan_kernel()
{
    extern __shared__ int si[];
    int* sdeg = si;                 // NN
    int* sp   = si + NN;            // 1024
    int* sb   = si + NN + 1024;     // 1024
    const int t = threadIdx.x;
    for (int i = t; i < NN; i += SCAN_T) { sdeg[i] = g_deg[i]; g_deg[i] = 0; }
    __syncthreads();
    const int base = t * CHUNK;
    int sum = 0;
#pragma unroll
    for (int i = 0; i < CHUNK; i++) {
        const int idx = base + i;
        if (idx < NN) {
            const int d = sdeg[idx];
            sdeg[idx] = sum;        // exclusive prefix within chunk
            sum += d;
        }
    }
    sp[t] = sum;
    __syncthreads();
    for (int o = 1; o < SCAN_T; o <<= 1) {
        int v = 0;
        if (t >= o) v = sp[t - o];
        __syncthreads();
        if (t >= o) sp[t] += v;
        __syncthreads();
    }
    sb[t] = sp[t] - sum;            // exclusive base per chunk
    __syncthreads();
    for (int i = t; i < NN; i += SCAN_T) {
        const int v = sdeg[i] + sb[i / CHUNK];
        g_off[i] = v;
        g_cur[i] = v;
    }
    if (t == SCAN_T - 1) g_off[NN] = sp[SCAN_T - 1];
}
#define SCAN_SMEM ((NN + 2 * SCAN_T) * 4)

// ================= pre2: scatterF + layer-0 el/er (fused) ===================
#define B_SCAT 391     // ceil(NE/256)
#define B_NA   313     // ceil(NN/64)
__global__ __launch_bounds__(256) void pre2_kernel(
        const int* __restrict__ dst, const int* __restrict__ src,
        const float* __restrict__ ef, const float* __restrict__ x)
{
    __shared__ float smf[64 * 65];
    const int t = threadIdx.x;
    const int b = blockIdx.x;
    if (b < B_SCAT) {
        // ---- scatter + gather + 4-layer ee
        float* srd = smf;                       // [4][NH*EFD] = 256
        if (t < 4 * NH * EFD) srd[t] = ((const float*)g_rede)[t];
        __syncthreads();
        const int e = b * 256 + t;
        if (e >= NE) return;
        const int pos = atomicAdd(&g_cur[dst[e]], 1);
        g_srcs[pos] = src[e];
        float r[EFD];
#pragma unroll
        for (int q = 0; q < EFD / 4; q++) {
            const float4 v = __ldg((const float4*)&ef[(size_t)e * EFD + q * 4]);
            r[q * 4 + 0] = v.x; r[q * 4 + 1] = v.y;
            r[q * 4 + 2] = v.z; r[q * 4 + 3] = v.w;
            *(float4*)&g_efs[(size_t)pos * EFD + q * 4] = v;
        }
#pragma unroll
        for (int lid = 0; lid < 4; lid++) {
            float v0 = 0.f, v1 = 0.f;
#pragma unroll
            for (int k = 0; k < EFD; k++) {
                v0 = fmaf(r[k], srd[lid * 64 + k], v0);
                v1 = fmaf(r[k], srd[lid * 64 + EFD + k], v1);
            }
            *(float2*)&g_eeall[lid][(size_t)pos * NH] = make_float2(v0, v1);
        }
    } else {
        // ---- layer-0 el/er for 64 nodes
        const int n0 = (b - B_SCAT) * 64;
        for (int i = t; i < 64 * NF; i += 256) {
            const int row = i >> 6, col = i & 63;
            const int n = n0 + row;
            smf[row * 65 + col] = (n < NN) ? x[(size_t)n * NF + col] : 0.f;
        }
        __syncthreads();
        const int type = t >> 7, h = (t >> 6) & 1, i = t & 63;
        const int n = n0 + i;
        if (n < NN) {
            const float* rd = (type ? g_redr : g_redl)[0] + h * NF;
            float v = 0.f;
#pragma unroll
            for (int k = 0; k < NF; k++) v = fmaf(smf[i * 65 + k], rd[k], v);
            (type ? g_erb : g_elb)[0][n * NH + h] = v;
        }
    }
}

// ================= fused per-layer kernel ====================================
// 128 threads, 8 nodes/block, grid 2500 (R13 structure, finer granularity:
// smaller barrier-coupled degree max, better occupancy headroom).
// Phase A: half-warp per node, 2 edges/iter.
// Phase B: thread = column c (t), computes all 8 rows; per k:
//          1 weight LDG + 2 broadcast LDS.128 per warp.
// Phase C: head-mean -> hout; next-layer el/er epilogue.
#define NPB 8                      // nodes per block
#define STS_ 129                   // st row stride
__global__ __launch_bounds__(128) void layer_kernel(
        const float* __restrict__ x,
        const float* __restrict__ Wn, const float* __restrict__ We,
        const float* __restrict__ b,
        const float* __restrict__ el_in, const float* __restrict__ er_in,
        float* __restrict__ el_out, float* __restrict__ er_out,
        int lid, int last, float* __restrict__ hout)
{
    __shared__ __align__(16) float sV[192 * NPB]; // [k][i]; k<128 xs(h*64+kk), k>=128 us
    __shared__ float st[NPB * STS_];              // [i][c]

    const int t = threadIdx.x;
    const int wid = t >> 5, lane = t & 31;
    const int half = lane >> 4, s = lane & 15;
    const int i = wid * 2 + half;                 // block-local node 0..7
    const int n0 = blockIdx.x * NPB;
    const int n = n0 + i;
    const float* eep = g_eeall[lid];

    const float2 er2 = *(const float2*)&er_in[n * NH];
    const int start = g_off[n];
    const int deg = g_off[n + 1] - start;
    const int dother = __shfl_xor_sync(0xffffffffu, deg, 16);
    const int degmax = (deg > dother) ? deg : dother;

    float4 xa0 = make_float4(0.f, 0.f, 0.f, 0.f);   // head-0 weighted x sums
    float4 xa1 = make_float4(0.f, 0.f, 0.f, 0.f);   // head-1
    float2 ua0 = make_float2(0.f, 0.f);
    float2 ua1 = make_float2(0.f, 0.f);
    float s0 = 0.f, s1 = 0.f;

    for (int jj = 0; jj < degmax; jj += 2) {
        // two edge slots, index-clamped so loads stay in-bounds
        int o0 = jj;     if (o0 > deg - 1) o0 = deg - 1; if (o0 < 0) o0 = 0;
        int o1 = jj + 1; if (o1 > deg - 1) o1 = deg - 1; if (o1 < 0) o1 = 0;
        int j0 = start + o0; if (j0 > NE - 1) j0 = NE - 1;
        int j1 = start + o1; if (j1 > NE - 1) j1 = NE - 1;
        const bool a0 = (jj < deg), a1 = (jj + 1 < deg);

        const int sn0 = g_srcs[j0], sn1 = g_srcs[j1];
        const float2 ee0 = *(const float2*)&eep[(size_t)j0 * NH];
        const float2 ee1 = *(const float2*)&eep[(size_t)j1 * NH];
        const float2 eA = *(const float2*)&el_in[sn0 * NH];
        const float2 eB = *(const float2*)&el_in[sn1 * NH];
        const float4 xv0 = __ldg((const float4*)&x[(size_t)sn0 * NF + s * 4]);
        const float4 xv1 = __ldg((const float4*)&x[(size_t)sn1 * NF + s * 4]);
        const float2 ev0 = *(const float2*)&g_efs[(size_t)j0 * EFD + s * 2];
        const float2 ev1 = *(const float2*)&g_efs[(size_t)j1 * EFD + s * 2];

        float l00 = eA.x + er2.x + ee0.x, l01 = eA.y + er2.y + ee0.y;
        float l10 = eB.x + er2.x + ee1.x, l11 = eB.y + er2.y + ee1.y;
        l00 = (l00 > 0.f) ? l00 : 0.2f * l00;
        l01 = (l01 > 0.f) ? l01 : 0.2f * l01;
        l10 = (l10 > 0.f) ? l10 : 0.2f * l10;
        l11 = (l11 > 0.f) ? l11 : 0.2f * l11;
        const float p00 = a0 ? __expf(l00) : 0.f;
        const float p01 = a0 ? __expf(l01) : 0.f;
        const float p10 = a1 ? __expf(l10) : 0.f;
        const float p11 = a1 ? __expf(l11) : 0.f;
        s0 += p00 + p10; s1 += p01 + p11;

        xa0.x = fmaf(xv0.x, p00, fmaf(xv1.x, p10, xa0.x));
        xa0.y = fmaf(xv0.y, p00, fmaf(xv1.y, p10, xa0.y));
        xa0.z = fmaf(xv0.z, p00, fmaf(xv1.z, p10, xa0.z));
        xa0.w = fmaf(xv0.w, p00, fmaf(xv1.w, p10, xa0.w));
        xa1.x = fmaf(xv0.x, p01, fmaf(xv1.x, p11, xa1.x));
        xa1.y = fmaf(xv0.y, p01, fmaf(xv1.y, p11, xa1.y));
        xa1.z = fmaf(xv0.z, p01, fmaf(xv1.z, p11, xa1.z));
        xa1.w = fmaf(xv0.w, p01, fmaf(xv1.w, p11, xa1.w));
        ua0.x = fmaf(ev0.x, p00, fmaf(ev1.x, p10, ua0.x));
        ua0.y = fmaf(ev0.y, p00, fmaf(ev1.y, p10, ua0.y));
        ua1.x = fmaf(ev0.x, p01, fmaf(ev1.x, p11, ua1.x));
        ua1.y = fmaf(ev0.y, p01, fmaf(ev1.y, p11, ua1.y));
    }

    const float inv0 = (s0 > 0.f) ? 1.f / s0 : 0.f;   // deg-0 -> msg = 0
    const float inv1 = (s1 > 0.f) ? 1.f / s1 : 0.f;
    sV[(4 * s + 0) * NPB + i] = xa0.x * inv0;
    sV[(4 * s + 1) * NPB + i] = xa0.y * inv0;
    sV[(4 * s + 2) * NPB + i] = xa0.z * inv0;
    sV[(4 * s + 3) * NPB + i] = xa0.w * inv0;
    sV[(64 + 4 * s + 0) * NPB + i] = xa1.x * inv1;
    sV[(64 + 4 * s + 1) * NPB + i] = xa1.y * inv1;
    sV[(64 + 4 * s + 2) * NPB + i] = xa1.z * inv1;
    sV[(64 + 4 * s + 3) * NPB + i] = xa1.w * inv1;
    sV[(128 + 2 * s + 0) * NPB + i] = ua0.x * inv0;
    sV[(128 + 2 * s + 1) * NPB + i] = ua0.y * inv0;
    sV[(160 + 2 * s + 0) * NPB + i] = ua1.x * inv1;
    sV[(160 + 2 * s + 1) * NPB + i] = ua1.y * inv1;
    __syncthreads();

    // -------- Phase B: thread = column, all 8 rows --------
    {
        const int c = t, h = c >> 6;
        float acc[NPB];
#pragma unroll
        for (int r = 0; r < NPB; r++) acc[r] = 0.f;

        const float* sVx = sV + (h * 64) * NPB;
#pragma unroll 4
        for (int kk = 0; kk < NF; kk++) {
            const float w = __ldg(&Wn[kk * FH + c]);
            const float4 v0 = *(const float4*)&sVx[kk * NPB];
            const float4 v1 = *(const float4*)&sVx[kk * NPB + 4];
            acc[0] = fmaf(v0.x, w, acc[0]); acc[1] = fmaf(v0.y, w, acc[1]);
            acc[2] = fmaf(v0.z, w, acc[2]); acc[3] = fmaf(v0.w, w, acc[3]);
            acc[4] = fmaf(v1.x, w, acc[4]); acc[5] = fmaf(v1.y, w, acc[5]);
            acc[6] = fmaf(v1.z, w, acc[6]); acc[7] = fmaf(v1.w, w, acc[7]);
        }
        const float* sVu = sV + (128 + h * 32) * NPB;
#pragma unroll 4
        for (int kk = 0; kk < EFD; kk++) {
            const float w = __ldg(&We[kk * FH + c]);
            const float4 v0 = *(const float4*)&sVu[kk * NPB];
            const float4 v1 = *(const float4*)&sVu[kk * NPB + 4];
            acc[0] = fmaf(v0.x, w, acc[0]); acc[1] = fmaf(v0.y, w, acc[1]);
            acc[2] = fmaf(v0.z, w, acc[2]); acc[3] = fmaf(v0.w, w, acc[3]);
            acc[4] = fmaf(v1.x, w, acc[4]); acc[5] = fmaf(v1.y, w, acc[5]);
            acc[6] = fmaf(v1.z, w, acc[6]); acc[7] = fmaf(v1.w, w, acc[7]);
        }
        const float bc = __ldg(&b[c]);
#pragma unroll
        for (int r = 0; r < NPB; r++)
            st[r * STS_ + c] = acc[r] + bc;
    }
    __syncthreads();

    // -------- Phase C: head mean -> hout (8*64 outputs, 4 per thread) -------
#pragma unroll
    for (int rep = 0; rep < 4; rep++) {
        const int idx = rep * 128 + t;
        const int ii = idx >> 6, d = idx & 63;
        hout[(size_t)(n0 + ii) * DH + d] =
            0.5f * (st[ii * STS_ + d] + st[ii * STS_ + DH + d]);
    }
    // next-layer el/er (32 tasks: type x head x 8 nodes)
    if (!last && t < 32) {
        const int type = t >> 4, hh = (t >> 3) & 1, ii = t & 7;
        const float* rd = (type ? g_redr : g_redl)[lid + 1] + hh * NF;
        float v = 0.f;
#pragma unroll
        for (int d = 0; d < DH; d++)
            v = fmaf(0.5f * (st[ii * STS_ + d] + st[ii * STS_ + DH + d]), rd[d], v);
        (type ? er_out : el_out)[(n0 + ii) * NH + hh] = v;
    }
}

// ---------------- host-side driver ------------------------------------------
extern "C" void kernel_launch(void* const* d_in, const int* in_sizes, int n_in,
                              void* d_out, int out_size)
{
    const float* x   = (const float*)d_in[0];
    const float* e   = (const float*)d_in[1];
    const int*   src = (const int*)  d_in[2];
    const int*   dst = (const int*)  d_in[3];

    // Only the LAST snapshot contributes to the output (decoded[-1]).
    const int S = in_sizes[0] / (NN * NF);
    const float* xs = x   + (size_t)(S - 1) * NN * NF;
    const float* es = e   + (size_t)(S - 1) * NE * EFD;
    const int*   ss = src + (size_t)(S - 1) * NE;
    const int*   ds = dst + (size_t)(S - 1) * NE;

    void *ph = nullptr, *ph2 = nullptr, *pwp = nullptr, *pel = nullptr, *per = nullptr;
    cudaGetSymbolAddress(&ph,  g_h);
    cudaGetSymbolAddress(&ph2, g_h2);
    cudaGetSymbolAddress(&pwp, g_Wp);
    cudaGetSymbolAddress(&pel, g_elb);
    cudaGetSymbolAddress(&per, g_erb);
    float* h  = (float*)ph;
    float* h2 = (float*)ph2;
    const float* Wp = (const float*)pwp;
    float* elb[2] = { (float*)pel, (float*)pel + NN * NH };
    float* erb[2] = { (float*)per, (float*)per + NN * NH };

    cudaFuncSetAttribute(scan_kernel, cudaFuncAttributeMaxDynamicSharedMemorySize,
                         SCAN_SMEM);

    // Input order (setup_inputs dict insertion order):
    //   0:x 1:e 2:src 3:dst, 4..9:enc0{Wn,We,al,ar,ae,b}, 10..15:enc1,
    //   16..21:dec0, 22..27:dec1, 28:W_e2d
    const float* P[29];
    for (int i = 4; i <= 28; i++) P[i] = (const float*)d_in[i];

    PrepParams pp;
    pp.Wn[0] = P[4];  pp.We[0] = P[5];  pp.al[0] = P[6];  pp.ar[0] = P[7];  pp.ae[0] = P[8];
    pp.Wn[1] = P[10]; pp.We[1] = P[11]; pp.al[1] = P[12]; pp.ar[1] = P[13]; pp.ae[1] = P[14];
    pp.Wn[2] = P[16]; pp.We[2] = P[17]; pp.al[2] = P[18]; pp.ar[2] = P[19]; pp.ae[2] = P[20];
    pp.Wn[3] = P[22]; pp.We[3] = P[23]; pp.al[3] = P[24]; pp.ar[3] = P[25]; pp.ae[3] = P[26];
    pp.We2d = P[28];

    pre1_kernel<<<B_HIST + B_WF + B_PREP, 256>>>(ds, pp);
    scan_kernel<<<1, SCAN_T, SCAN_SMEM>>>();
    pre2_kernel<<<B_SCAT + B_NA, 256>>>(ds, ss, es, xs);

    layer_kernel<<<NN / NPB, 128>>>(xs, P[4],  P[5],  P[9],
                                    elb[0], erb[0], elb[1], erb[1], 0, 0, h);
    layer_kernel<<<NN / NPB, 128>>>(h,  P[10], P[11], P[15],
                                    elb[1], erb[1], elb[0], erb[0], 1, 0, h2);
    layer_kernel<<<NN / NPB, 128>>>(h2, Wp,    P[17], P[21],
                                    elb[0], erb[0], elb[1], erb[1], 2, 0, h);
    layer_kernel<<<NN / NPB, 128>>>(h,  P[22], P[23], P[27],
                                    elb[1], erb[1], elb[0], erb[0], 3, 1, (float*)d_out);
}